// round 15
// baseline (speedup 1.0000x reference)
#include <cuda_runtime.h>
#include <cuda_fp16.h>
#include <cuda_bf16.h>
#include <math.h>

// Problem dims (fixed by the dataset)
#define NB 4
#define CH 3
#define HH 1080
#define WW 1920
#define HW (HH * WW)
#define NHW (NB * HW)

#define SZ_IN     (NB * 3 * HW)   // 24883200
#define SZ_FLOW   (NB * 2 * HW)   // 16588800
#define SZ_METRIC (NB * 1 * HW)   //  8294400

// Staggered dual accumulator, f16, 4 channels (c0*mw, c1*mw, c2*mw, m*w):
//   A_b: [H, W, 4]     — pairs starting at EVEN x0 (cols x0, x0+1)
//   B_b: [H, 1922, 4]  — shifted one col (index x+1, pads both ends) —
//                        pairs starting at ODD x0 (16B-aligned there).
// One 16B v4.f16x2 RED per footprint row: 2 msgs/px (the message floor for a
// 32B/px footprint). Batch-major layout [A_0|B_0|A_1|B_1|...]: contiguous
// 33.2MB per-batch slices, L2-resident through their splat->norm window.
//
// Zeroing rotation: norm_b zeroes slice (b+1)%4 (disjoint from its reads of
// slice b — NO same-line RMW). In-launch order s0 n0 s1 n1 s2 n2 s3 n3 means
// every splat sees a freshly zeroed slice; n3 restores the entry invariant
// ("slice 0 clean") for the next launch / graph replay. BSS-zero covers the
// first call.
#define BW 1922
#define A_B_HALVES ((size_t)HH * WW * 4)              // per-batch A (halves)
#define B_B_HALVES ((size_t)HH * BW * 4)              // per-batch B (halves)
#define AB_HALVES  (A_B_HALVES + B_B_HALVES)          // per-batch total
#define TOT_HALVES ((size_t)NB * AB_HALVES)
#define Z16        (AB_HALVES / 8)                    // 16B chunks per slice

__device__ __align__(16) __half g_acc[TOT_HALVES];

static __device__ __forceinline__ unsigned pack2(float a, float b) {
    __half2 h = __floats2half2_rn(a, b);
    return *reinterpret_cast<unsigned*>(&h);
}

__global__ void splat_kernel(const float* __restrict__ in,
                             const float* __restrict__ flow,
                             const float* __restrict__ metric,
                             int b) {
    int rem = blockIdx.x * blockDim.x + threadIdx.x;
    if (rem >= HW) return;
    int y = rem / WW;
    int x = rem - y * WW;

    float fx = flow[(size_t)(b * 2 + 0) * HW + rem];
    float fy = flow[(size_t)(b * 2 + 1) * HW + rem];
    float tx = (float)x + fx;
    float ty = (float)y + fy;
    if (!isfinite(tx) || !isfinite(ty)) return;  // ref zeroes these contributions

    float m  = __expf(metric[(size_t)b * HW + rem]);
    float v0 = in[(size_t)(b * 3 + 0) * HW + rem] * m;
    float v1 = in[(size_t)(b * 3 + 1) * HW + rem] * m;
    float v2 = in[(size_t)(b * 3 + 2) * HW + rem] * m;

    float fxf = floorf(tx);
    float fyf = floorf(ty);
    int x0 = (int)fxf;
    int y0 = (int)fyf;
    float ax = tx - fxf;
    float ay = ty - fyf;

    float wx0 = 1.f - ax, wx1 = ax;
    float wy_[2] = {1.f - ay, ay};

    bool odd = (x0 & 1) != 0;
    // even: pair valid iff x0 in [0, WW-2]; odd: iff x0 in [-1, WW-1]
    bool ok = odd ? (x0 >= -1 && x0 <= WW - 1) : ((unsigned)x0 <= (unsigned)(WW - 2));
    if (!ok) return;

    __half* slice = g_acc + (size_t)b * AB_HALVES;
    __half* arr;
    int col, rw;
    if (odd) { arr = slice + A_B_HALVES; col = x0 + 1; rw = BW; }
    else     { arr = slice;              col = x0;     rw = WW; }

#pragma unroll
    for (int dy = 0; dy < 2; dy++) {
        int iy = y0 + dy;
        if (iy < 0 || iy >= HH) continue;
        float W0 = wx0 * wy_[dy];
        float W1 = wx1 * wy_[dy];
        unsigned a0 = pack2(v0 * W0, v1 * W0);
        unsigned a1 = pack2(v2 * W0, m  * W0);
        unsigned b0 = pack2(v0 * W1, v1 * W1);
        unsigned b1 = pack2(v2 * W1, m  * W1);
        __half* ptr = arr + ((size_t)iy * rw + col) * 4;
        asm volatile(
            "red.global.add.noftz.v4.f16x2 [%0], {%1, %2, %3, %4};"
            :: "l"(ptr), "r"(a0), "r"(a1), "r"(b0), "r"(b1)
            : "memory");
    }
}

// Normalize batch b (read-only on slice b) + zero slice zb (disjoint region,
// pure streaming stores). 4 px/thread.
__global__ void norm_kernel(float* __restrict__ out, int b, int zb) {
    int t = blockIdx.x * blockDim.x + threadIdx.x;
    const int nthreads = (HW / 4);

    // ---- zero stores for slice zb (independent traffic, issued first) ----
    {
        float4* zp = reinterpret_cast<float4*>(g_acc + (size_t)zb * AB_HALVES);
        const float4 z = make_float4(0.f, 0.f, 0.f, 0.f);
        for (size_t i = t; i < Z16; i += nthreads)
            zp[i] = z;
    }

    if (t >= nthreads) return;
    int rem = t * 4;
    int y   = rem / WW;
    int x   = rem - y * WW;

    const __half* A_b = g_acc + (size_t)b * AB_HALVES;
    const __half* B_b = A_b + A_B_HALVES;

    const __half* aRow = A_b + ((size_t)y * WW + x) * 4;
    const __half* bRow = B_b + ((size_t)y * BW + x) * 4;

    float4 aLo = *reinterpret_cast<const float4*>(aRow);       // cells x, x+1
    float4 aHi = *reinterpret_cast<const float4*>(aRow + 8);   // cells x+2, x+3
    uint2  bA  = *reinterpret_cast<const uint2*>(bRow + 4);    // cell  x+1
    float4 bM  = *reinterpret_cast<const float4*>(bRow + 8);   // cells x+2, x+3
    uint2  bZ  = *reinterpret_cast<const uint2*>(bRow + 16);   // cell  x+4

    float o0[4], o1[4], o2[4];

#pragma unroll
    for (int j = 0; j < 4; j++) {
        unsigned a_lo, a_hi, b_lo, b_hi;
        if (j == 0)      { a_lo = __float_as_uint(aLo.x); a_hi = __float_as_uint(aLo.y);
                           b_lo = bA.x;                   b_hi = bA.y; }
        else if (j == 1) { a_lo = __float_as_uint(aLo.z); a_hi = __float_as_uint(aLo.w);
                           b_lo = __float_as_uint(bM.x);  b_hi = __float_as_uint(bM.y); }
        else if (j == 2) { a_lo = __float_as_uint(aHi.x); a_hi = __float_as_uint(aHi.y);
                           b_lo = __float_as_uint(bM.z);  b_hi = __float_as_uint(bM.w); }
        else             { a_lo = __float_as_uint(aHi.z); a_hi = __float_as_uint(aHi.w);
                           b_lo = bZ.x;                   b_hi = bZ.y; }

        float2 a01 = __half22float2(*reinterpret_cast<__half2*>(&a_lo));
        float2 a23 = __half22float2(*reinterpret_cast<__half2*>(&a_hi));
        float2 b01 = __half22float2(*reinterpret_cast<__half2*>(&b_lo));
        float2 b23 = __half22float2(*reinterpret_cast<__half2*>(&b_hi));

        float inv = 1.0f / ((a23.y + b23.y) + 1e-7f);
        o0[j] = (a01.x + b01.x) * inv;
        o1[j] = (a01.y + b01.y) * inv;
        o2[j] = (a23.x + b23.x) * inv;
    }

    size_t o = (size_t)(b * 3) * HW + rem;
    *reinterpret_cast<float4*>(out + o)          = make_float4(o0[0], o0[1], o0[2], o0[3]);
    *reinterpret_cast<float4*>(out + o + HW)     = make_float4(o1[0], o1[1], o1[2], o1[3]);
    *reinterpret_cast<float4*>(out + o + 2 * HW) = make_float4(o2[0], o2[1], o2[2], o2[3]);
}

extern "C" void kernel_launch(void* const* d_in, const int* in_sizes, int n_in,
                              void* d_out, int out_size) {
    // Identify inputs by element count — robust to any metadata ordering.
    const float* tenIn     = nullptr;
    const float* tenFlow   = nullptr;
    const float* tenMetric = nullptr;
    for (int i = 0; i < n_in; i++) {
        if      (in_sizes[i] == SZ_IN)     tenIn     = (const float*)d_in[i];
        else if (in_sizes[i] == SZ_FLOW)   tenFlow   = (const float*)d_in[i];
        else if (in_sizes[i] == SZ_METRIC) tenMetric = (const float*)d_in[i];
    }
    float* out = (float*)d_out;

    const int threads = 256;
    const int sblocks = (HW + threads - 1) / threads;       // 8100
    const int nblocks = (HW / 4 + threads - 1) / threads;   // 2025

    // s_b splats into a slice zeroed by n_{b-1} (slice 0 by the previous
    // launch's n_3 / BSS). No standalone zero kernels.
    for (int b = 0; b < NB; b++) {
        splat_kernel<<<sblocks, threads>>>(tenIn, tenFlow, tenMetric, b);
        norm_kernel <<<nblocks, threads>>>(out, b, (b + 1) % NB);
    }
}

// round 16
// speedup vs baseline: 1.1335x; 1.1335x over previous
#include <cuda_runtime.h>
#include <cuda_fp16.h>
#include <cuda_bf16.h>
#include <math.h>

// Problem dims (fixed by the dataset)
#define NB 4
#define CH 3
#define HH 1080
#define WW 1920
#define HW (HH * WW)
#define NHW (NB * HW)

#define SZ_IN     (NB * 3 * HW)   // 24883200
#define SZ_FLOW   (NB * 2 * HW)   // 16588800
#define SZ_METRIC (NB * 1 * HW)   //  8294400

// Staggered dual accumulator, f16, 4 channels (c0*mw, c1*mw, c2*mw, m*w):
//   A_b: [H, W, 4]     — pairs starting at EVEN x0 (cols x0, x0+1)
//   B_b: [H, 1922, 4]  — shifted one col (index x+1, pads both ends) —
//                        pairs starting at ODD x0 (16B-aligned there).
// One 16B v4.f16x2 RED per footprint row: 2 msgs/px (message floor for the
// 32B/px footprint). Batch-major layout: contiguous 33.2MB per-batch slices.
//
// Zeroing rotation: norm_b zeroes slice (b+1)%4 (disjoint from its reads —
// no same-line RMW). Order s0 n0 s1 n1 s2 n2 s3 n3: every splat sees a
// freshly zeroed slice; n3 restores the entry invariant ("slice 0 clean")
// for the next launch / graph replay; BSS-zero covers the first call.
// Streaming cache hints (__ldcs/__stcs) keep read-once/write-once traffic
// from evicting the zeroed slice before its splat consumes it.
#define BW 1922
#define A_B_HALVES ((size_t)HH * WW * 4)              // per-batch A (halves)
#define B_B_HALVES ((size_t)HH * BW * 4)              // per-batch B (halves)
#define AB_HALVES  (A_B_HALVES + B_B_HALVES)          // per-batch total
#define TOT_HALVES ((size_t)NB * AB_HALVES)
#define Z16        (AB_HALVES / 8)                    // 16B chunks per slice

__device__ __align__(16) __half g_acc[TOT_HALVES];

static __device__ __forceinline__ unsigned pack2(float a, float b) {
    __half2 h = __floats2half2_rn(a, b);
    return *reinterpret_cast<unsigned*>(&h);
}

__global__ void splat_kernel(const float* __restrict__ in,
                             const float* __restrict__ flow,
                             const float* __restrict__ metric,
                             int b) {
    int rem = blockIdx.x * blockDim.x + threadIdx.x;
    if (rem >= HW) return;
    int y = rem / WW;
    int x = rem - y * WW;

    // Streaming loads (evict-first): read-once inputs must not evict the
    // L2-resident accumulator slice.
    float fx = __ldcs(flow + (size_t)(b * 2 + 0) * HW + rem);
    float fy = __ldcs(flow + (size_t)(b * 2 + 1) * HW + rem);
    float tx = (float)x + fx;
    float ty = (float)y + fy;
    if (!isfinite(tx) || !isfinite(ty)) return;  // ref zeroes these contributions

    float m  = __expf(__ldcs(metric + (size_t)b * HW + rem));
    float v0 = __ldcs(in + (size_t)(b * 3 + 0) * HW + rem) * m;
    float v1 = __ldcs(in + (size_t)(b * 3 + 1) * HW + rem) * m;
    float v2 = __ldcs(in + (size_t)(b * 3 + 2) * HW + rem) * m;

    float fxf = floorf(tx);
    float fyf = floorf(ty);
    int x0 = (int)fxf;
    int y0 = (int)fyf;
    float ax = tx - fxf;
    float ay = ty - fyf;

    float wx0 = 1.f - ax, wx1 = ax;
    float wy_[2] = {1.f - ay, ay};

    bool odd = (x0 & 1) != 0;
    // even: pair valid iff x0 in [0, WW-2]; odd: iff x0 in [-1, WW-1]
    bool ok = odd ? (x0 >= -1 && x0 <= WW - 1) : ((unsigned)x0 <= (unsigned)(WW - 2));
    if (!ok) return;

    __half* slice = g_acc + (size_t)b * AB_HALVES;
    __half* arr;
    int col, rw;
    if (odd) { arr = slice + A_B_HALVES; col = x0 + 1; rw = BW; }
    else     { arr = slice;              col = x0;     rw = WW; }

#pragma unroll
    for (int dy = 0; dy < 2; dy++) {
        int iy = y0 + dy;
        if (iy < 0 || iy >= HH) continue;
        float W0 = wx0 * wy_[dy];
        float W1 = wx1 * wy_[dy];
        unsigned a0 = pack2(v0 * W0, v1 * W0);
        unsigned a1 = pack2(v2 * W0, m  * W0);
        unsigned b0 = pack2(v0 * W1, v1 * W1);
        unsigned b1 = pack2(v2 * W1, m  * W1);
        __half* ptr = arr + ((size_t)iy * rw + col) * 4;
        asm volatile(
            "red.global.add.noftz.v4.f16x2 [%0], {%1, %2, %3, %4};"
            :: "l"(ptr), "r"(a0), "r"(a1), "r"(b0), "r"(b1)
            : "memory");
    }
}

// Normalize batch b (streaming reads of slice b) + zero slice zb (disjoint,
// default write-back stores so the zeroed lines STAY in L2 for their splat).
__global__ void norm_kernel(float* __restrict__ out, int b, int zb) {
    int t = blockIdx.x * blockDim.x + threadIdx.x;
    const int nthreads = (HW / 4);

    // ---- zero stores for slice zb (keep resident: default policy) ----
    {
        float4* zp = reinterpret_cast<float4*>(g_acc + (size_t)zb * AB_HALVES);
        const float4 z = make_float4(0.f, 0.f, 0.f, 0.f);
        for (size_t i = t; i < Z16; i += nthreads)
            zp[i] = z;
    }

    if (t >= nthreads) return;
    int rem = t * 4;
    int y   = rem / WW;
    int x   = rem - y * WW;

    const __half* A_b = g_acc + (size_t)b * AB_HALVES;
    const __half* B_b = A_b + A_B_HALVES;

    const __half* aRow = A_b + ((size_t)y * WW + x) * 4;
    const __half* bRow = B_b + ((size_t)y * BW + x) * 4;

    // Streaming (evict-first) reads: these lines are dead after this pass.
    float4 aLo = __ldcs(reinterpret_cast<const float4*>(aRow));      // x, x+1
    float4 aHi = __ldcs(reinterpret_cast<const float4*>(aRow + 8));  // x+2, x+3
    uint2  bA  = __ldcs(reinterpret_cast<const uint2*>(bRow + 4));   // x+1
    float4 bM  = __ldcs(reinterpret_cast<const float4*>(bRow + 8));  // x+2, x+3
    uint2  bZ  = __ldcs(reinterpret_cast<const uint2*>(bRow + 16));  // x+4

    float o0[4], o1[4], o2[4];

#pragma unroll
    for (int j = 0; j < 4; j++) {
        unsigned a_lo, a_hi, b_lo, b_hi;
        if (j == 0)      { a_lo = __float_as_uint(aLo.x); a_hi = __float_as_uint(aLo.y);
                           b_lo = bA.x;                   b_hi = bA.y; }
        else if (j == 1) { a_lo = __float_as_uint(aLo.z); a_hi = __float_as_uint(aLo.w);
                           b_lo = __float_as_uint(bM.x);  b_hi = __float_as_uint(bM.y); }
        else if (j == 2) { a_lo = __float_as_uint(aHi.x); a_hi = __float_as_uint(aHi.y);
                           b_lo = __float_as_uint(bM.z);  b_hi = __float_as_uint(bM.w); }
        else             { a_lo = __float_as_uint(aHi.z); a_hi = __float_as_uint(aHi.w);
                           b_lo = bZ.x;                   b_hi = bZ.y; }

        float2 a01 = __half22float2(*reinterpret_cast<__half2*>(&a_lo));
        float2 a23 = __half22float2(*reinterpret_cast<__half2*>(&a_hi));
        float2 b01 = __half22float2(*reinterpret_cast<__half2*>(&b_lo));
        float2 b23 = __half22float2(*reinterpret_cast<__half2*>(&b_hi));

        float inv = 1.0f / ((a23.y + b23.y) + 1e-7f);
        o0[j] = (a01.x + b01.x) * inv;
        o1[j] = (a01.y + b01.y) * inv;
        o2[j] = (a23.x + b23.x) * inv;
    }

    size_t o = (size_t)(b * 3) * HW + rem;
    // Streaming (evict-first) output stores: never re-read on device.
    __stcs(reinterpret_cast<float4*>(out + o),          make_float4(o0[0], o0[1], o0[2], o0[3]));
    __stcs(reinterpret_cast<float4*>(out + o + HW),     make_float4(o1[0], o1[1], o1[2], o1[3]));
    __stcs(reinterpret_cast<float4*>(out + o + 2 * HW), make_float4(o2[0], o2[1], o2[2], o2[3]));
}

extern "C" void kernel_launch(void* const* d_in, const int* in_sizes, int n_in,
                              void* d_out, int out_size) {
    // Identify inputs by element count — robust to any metadata ordering.
    const float* tenIn     = nullptr;
    const float* tenFlow   = nullptr;
    const float* tenMetric = nullptr;
    for (int i = 0; i < n_in; i++) {
        if      (in_sizes[i] == SZ_IN)     tenIn     = (const float*)d_in[i];
        else if (in_sizes[i] == SZ_FLOW)   tenFlow   = (const float*)d_in[i];
        else if (in_sizes[i] == SZ_METRIC) tenMetric = (const float*)d_in[i];
    }
    float* out = (float*)d_out;

    const int threads = 256;
    const int sblocks = (HW + threads - 1) / threads;       // 8100
    const int nblocks = (HW / 4 + threads - 1) / threads;   // 2025

    // s_b splats into a slice zeroed by n_{b-1} (slice 0 by the previous
    // launch's n_3 / BSS). No standalone zero kernels.
    for (int b = 0; b < NB; b++) {
        splat_kernel<<<sblocks, threads>>>(tenIn, tenFlow, tenMetric, b);
        norm_kernel <<<nblocks, threads>>>(out, b, (b + 1) % NB);
    }
}